// round 9
// baseline (speedup 1.0000x reference)
#include <cuda_runtime.h>

// SmartDerivatives R9: R6 consumer + per-warp flat->strided relay through smem.
// R6 was capped ~3.9TB/s by L1tex wavefront multiplicity: three stride-24B
// LDG.64 per desc deliver every 128B line of `left` ~3x. Here each warp first
// copies its triu row FLAT (contiguous float2, 1 line ~= 1 wavefront) into a
// private 2.4KB smem buffer, then consumes it with stride-6-word LDS.64
// (conflict-free: 6m mod 32 hits 16 distinct banks per phase). Warp-local
// sync only; j-side bins SoA (conflict-free RMW); mirrored row pairs balance.

constexpr int NA    = 100;
constexpr int D     = 4950;
constexpr int E     = D * 6;
constexpr int S3    = NA * 3;          // 300
constexpr int WARPS = 10;
constexpr int T     = WARPS * 32;      // 320
constexpr int BUF2  = 304;             // float2 slots per warp row buffer (>=297)
constexpr int AP    = 128;             // padded atoms per bin plane

__device__ __forceinline__ void process_row(
    int i, int lane,
    const float* __restrict__ lb, const float* __restrict__ xb,
    float2* __restrict__ buf2,                     // per-warp smem row buffer
    float* __restrict__ c0, float* __restrict__ c1, float* __restrict__ c2,
    float* __restrict__ rowout)
{
    const int base = (i * (2 * NA - i - 1)) >> 1;  // row start desc
    const int len  = NA - 1 - i;

    // ---- relay: flat contiguous copy of this row (len*3 float2) ----
    {
        const float2* __restrict__ g2 =
            reinterpret_cast<const float2*>(lb) + base * 3;
        const int n2 = len * 3;
        for (int k = lane; k < n2; k += 32) buf2[k] = __ldg(g2 + k);
    }
    __syncwarp();

    float r0 = 0.f, r1 = 0.f, r2 = 0.f;

    #pragma unroll 2
    for (int m = lane; m < len; m += 32) {
        const float2 l01 = buf2[3 * m + 0];        // stride-6-word LDS.64
        const float2 l23 = buf2[3 * m + 1];
        const float2 l45 = buf2[3 * m + 2];
        const float  xv  = __ldg(xb + base + m);   // contiguous, 1 line/warp

        // atom-i side (slots 0..2): register accumulate
        r0 = fmaf(l01.x, xv, r0);
        r1 = fmaf(l01.y, xv, r1);
        r2 = fmaf(l23.x, xv, r2);

        // atom-j side (slots 3..5): j unique per lane, stride-1 banks (SoA)
        const int j = i + 1 + m;
        c0[j] += l23.y * xv;
        c1[j] += l45.x * xv;
        c2[j] += l45.y * xv;
    }

    #pragma unroll
    for (int off = 16; off; off >>= 1) {
        r0 += __shfl_down_sync(0xffffffffu, r0, off);
        r1 += __shfl_down_sync(0xffffffffu, r1, off);
        r2 += __shfl_down_sync(0xffffffffu, r2, off);
    }
    if (lane == 0) {
        rowout[i * 3 + 0] = r0;
        rowout[i * 3 + 1] = r1;
        rowout[i * 3 + 2] = r2;
    }
    __syncwarp();   // buffer reused by next row of this warp
}

__global__ void __launch_bounds__(T)
smart_derivatives_kernel(const float* __restrict__ x,
                         const float* __restrict__ left,
                         float* __restrict__ out) {
    __shared__ __align__(16) float2 stage[WARPS][BUF2];  // 24.3 KB
    __shared__ float colacc[WARPS][3][AP];               // 15.4 KB, SoA bins
    __shared__ float rowout[S3];                         // 1.2 KB

    const int b    = blockIdx.x;
    const int t    = threadIdx.x;
    const int w    = t >> 5;
    const int lane = t & 31;

    for (int i = t; i < WARPS * 3 * AP; i += T) (&colacc[0][0][0])[i] = 0.0f;
    if (t < S3) rowout[t] = 0.0f;
    __syncthreads();

    const float* __restrict__ lb = left + (size_t)b * E;
    const float* __restrict__ xb = x + (size_t)b * D;
    float2* __restrict__ buf2 = stage[w];
    float*  __restrict__ c0   = colacc[w][0];
    float*  __restrict__ c1   = colacc[w][1];
    float*  __restrict__ c2   = colacc[w][2];

    // Mirrored pairs per 20-row band: rows (base+w) and (base+19-w);
    // pair lengths sum to a band constant -> balanced warps.
    for (int base = 0; base < NA - 1; base += 2 * WARPS) {
        const int i1 = base + w;
        const int i2 = base + (2 * WARPS - 1) - w;
        if (i1 < NA - 1) process_row(i1, lane, lb, xb, buf2, c0, c1, c2, rowout);
        if (i2 < NA - 1) process_row(i2, lane, lb, xb, buf2, c0, c1, c2, rowout);
    }
    __syncthreads();

    // combine: out(a,d) = (rowout + sum_w colacc[w][d][a])^2, coalesced store
    if (t < S3) {
        const int a = t / 3;
        const int d = t - 3 * a;
        float s = rowout[t];
        #pragma unroll
        for (int ww = 0; ww < WARPS; ++ww) s += colacc[ww][d][a];
        out[(size_t)b * S3 + t] = s * s;
    }
}

extern "C" void kernel_launch(void* const* d_in, const int* in_sizes, int n_in,
                              void* d_out, int out_size) {
    const float* x    = (const float*)d_in[0];   // [BATCH, D] fp32
    const float* left = (const float*)d_in[1];   // [BATCH*E] fp32
    (void)in_sizes; (void)n_in; (void)out_size;

    float* out = (float*)d_out;                  // [BATCH, 300] fp32
    smart_derivatives_kernel<<<1024, T>>>(x, left, out);
}